// round 3
// baseline (speedup 1.0000x reference)
#include <cuda_runtime.h>
#include <cuda_bf16.h>

// GuidedFilter (4,3,1024,1024) fp32, R=40, eps=1e-3.
// Two fused kernels; per output row: vertical running sums in registers,
// horizontal box via warp-local (64-col chunk) prefixes + window decomposition
// (window 81 spans <= 3 chunks). ONE __syncthreads per row, double-buffered.

#define HH   1024
#define WW   1024
#define NIMG 12
#define RAD  40
#define SEG  32
#define NTH  512
#define NCH  16            // chunks of 64 cols
#define CSTR 65            // chunk stride in E array (64 prefix + total slot)
#define ESZ  (NCH * CSTR)  // 1040 floats per field per buffer

#define EPS 1e-3f

__device__ float g_a[(size_t)NIMG * HH * WW];
__device__ float g_b[(size_t)NIMG * HH * WW];

// warp inclusive scan of a float, lanes 0..31
#define WSCAN(val)                                                    \
    {                                                                 \
        _Pragma("unroll")                                             \
        for (int o = 1; o < 32; o <<= 1) {                            \
            float _n = __shfl_up_sync(0xffffffffu, (val), o);         \
            if (lane >= o) (val) += _n;                               \
        }                                                             \
    }

// ---------------------------------------------------------------------------
// Stage 1: I,p -> box means of {I,p,Ip,II} -> a,b
// ---------------------------------------------------------------------------
__global__ __launch_bounds__(NTH, 2) void k_stage1(const float* __restrict__ I,
                                                   const float* __restrict__ P) {
    __shared__ float sE[2][4][ESZ];

    const int tid  = threadIdx.x;
    const int lane = tid & 31;
    const int wid  = tid >> 5;            // warp = chunk index (0..15)
    const int img  = blockIdx.y;
    const int y0   = blockIdx.x * SEG;
    const size_t b2 = (size_t)img * HH * (WW / 2);

    const float2* __restrict__ I2 = (const float2*)I + b2;
    const float2* __restrict__ P2 = (const float2*)P + b2;
    float2* __restrict__ A2 = (float2*)g_a + b2;
    float2* __restrict__ B2 = (float2*)g_b + b2;

    const int xi = wid * 32 + lane;       // float2 index within row (0..511)
    const int c0 = xi * 2;                // first column owned

    // per-column window constants
    int aLo[2], aHi[2], aT1[2], aT2[2];
    float cntx[2];
#pragma unroll
    for (int j = 0; j < 2; ++j) {
        int c   = c0 + j;
        int lo  = max(c - RAD, 0);
        int hi1 = min(c + RAD, WW - 1);      // inclusive
        int ca  = lo >> 6;
        int cb  = hi1 >> 6;
        aLo[j]  = ca * CSTR + (lo & 63);
        aHi[j]  = cb * CSTR + (hi1 & 63) + 1;
        aT1[j]  = (cb > ca)     ? ca * CSTR + 64       : 0;   // E[0] == 0
        aT2[j]  = (cb > ca + 1) ? (ca + 1) * CSTR + 64 : 0;
        cntx[j] = (float)(hi1 + 1 - lo);
    }

    // vertical running sums (2 cols x 4 fields)
    float2 rI  = make_float2(0.f, 0.f);
    float2 rP  = rI, rIp = rI, rII = rI;

    const int ys = max(0, y0 - RAD);
    const int ye = min(HH, y0 + RAD);      // exclusive
#pragma unroll 4
    for (int yy = ys; yy < ye; ++yy) {
        float2 i2 = I2[(size_t)yy * 512 + xi];
        float2 p2 = P2[(size_t)yy * 512 + xi];
        rI.x  += i2.x;        rI.y  += i2.y;
        rP.x  += p2.x;        rP.y  += p2.y;
        rIp.x += i2.x * p2.x; rIp.y += i2.y * p2.y;
        rII.x += i2.x * i2.x; rII.y += i2.y * i2.y;
    }

    const int eb = wid * CSTR;
    const int e1 = eb + 2 * lane + 1;

    for (int y = y0; y < y0 + SEG; ++y) {
        int ya = y + RAD;
        if (ya < HH) {
            float2 i2 = I2[(size_t)ya * 512 + xi];
            float2 p2 = P2[(size_t)ya * 512 + xi];
            rI.x  += i2.x;        rI.y  += i2.y;
            rP.x  += p2.x;        rP.y  += p2.y;
            rIp.x += i2.x * p2.x; rIp.y += i2.y * p2.y;
            rII.x += i2.x * i2.x; rII.y += i2.y * i2.y;
        }

        const int buf = y & 1;
        float* E0 = sE[buf][0];
        float* E1 = sE[buf][1];
        float* E2 = sE[buf][2];
        float* E3 = sE[buf][3];

        // warp-local inclusive scans of pair sums
        float s0 = rI.x + rI.y,  s1 = rP.x + rP.y;
        float s2 = rIp.x + rIp.y, s3 = rII.x + rII.y;
        float i0 = s0, i1 = s1, i2s = s2, i3 = s3;
        WSCAN(i0); WSCAN(i1); WSCAN(i2s); WSCAN(i3);
        float x0 = i0 - s0, x1 = i1 - s1, x2 = i2s - s2, x3 = i3 - s3;

        if (lane == 0) { E0[eb] = 0.f; E1[eb] = 0.f; E2[eb] = 0.f; E3[eb] = 0.f; }
        E0[e1] = x0 + rI.x;  E0[e1 + 1] = i0;
        E1[e1] = x1 + rP.x;  E1[e1 + 1] = i1;
        E2[e1] = x2 + rIp.x; E2[e1 + 1] = i2s;
        E3[e1] = x3 + rII.x; E3[e1 + 1] = i3;

        __syncthreads();

        float cnty = (float)(min(y + RAD + 1, HH) - max(y - RAD, 0));
        float2 av, bv;
        float* ap = &av.x;
        float* bp = &bv.x;
#pragma unroll
        for (int j = 0; j < 2; ++j) {
            float u0 = E0[aHi[j]] - E0[aLo[j]] + E0[aT1[j]] + E0[aT2[j]];
            float u1 = E1[aHi[j]] - E1[aLo[j]] + E1[aT1[j]] + E1[aT2[j]];
            float u2 = E2[aHi[j]] - E2[aLo[j]] + E2[aT1[j]] + E2[aT2[j]];
            float u3 = E3[aHi[j]] - E3[aLo[j]] + E3[aT1[j]] + E3[aT2[j]];
            float inv = 1.0f / (cntx[j] * cnty);
            float mI  = u0 * inv;
            float mP  = u1 * inv;
            float mIp = u2 * inv;
            float mII = u3 * inv;
            float a = (mIp - mI * mP) / ((mII - mI * mI) + EPS);
            ap[j] = a;
            bp[j] = mP - a * mI;
        }
        A2[(size_t)y * 512 + xi] = av;
        B2[(size_t)y * 512 + xi] = bv;

        int yr = y - RAD;
        if (yr >= 0) {
            float2 i2 = I2[(size_t)yr * 512 + xi];
            float2 p2 = P2[(size_t)yr * 512 + xi];
            rI.x  -= i2.x;        rI.y  -= i2.y;
            rP.x  -= p2.x;        rP.y  -= p2.y;
            rIp.x -= i2.x * p2.x; rIp.y -= i2.y * p2.y;
            rII.x -= i2.x * i2.x; rII.y -= i2.y * i2.y;
        }
    }
}

// ---------------------------------------------------------------------------
// Stage 2: a,b -> box means -> out = mean_a * I + mean_b
// ---------------------------------------------------------------------------
__global__ __launch_bounds__(NTH, 2) void k_stage2(const float* __restrict__ I,
                                                   float* __restrict__ out) {
    __shared__ float sE[2][2][ESZ];

    const int tid  = threadIdx.x;
    const int lane = tid & 31;
    const int wid  = tid >> 5;
    const int img  = blockIdx.y;
    const int y0   = blockIdx.x * SEG;
    const size_t b2 = (size_t)img * HH * (WW / 2);

    const float2* __restrict__ A2 = (const float2*)g_a + b2;
    const float2* __restrict__ B2 = (const float2*)g_b + b2;
    const float2* __restrict__ I2 = (const float2*)I + b2;
    float2* __restrict__ O2 = (float2*)out + b2;

    const int xi = wid * 32 + lane;
    const int c0 = xi * 2;

    int aLo[2], aHi[2], aT1[2], aT2[2];
    float cntx[2];
#pragma unroll
    for (int j = 0; j < 2; ++j) {
        int c   = c0 + j;
        int lo  = max(c - RAD, 0);
        int hi1 = min(c + RAD, WW - 1);
        int ca  = lo >> 6;
        int cb  = hi1 >> 6;
        aLo[j]  = ca * CSTR + (lo & 63);
        aHi[j]  = cb * CSTR + (hi1 & 63) + 1;
        aT1[j]  = (cb > ca)     ? ca * CSTR + 64       : 0;
        aT2[j]  = (cb > ca + 1) ? (ca + 1) * CSTR + 64 : 0;
        cntx[j] = (float)(hi1 + 1 - lo);
    }

    float2 rA = make_float2(0.f, 0.f);
    float2 rB = rA;

    const int ys = max(0, y0 - RAD);
    const int ye = min(HH, y0 + RAD);
#pragma unroll 4
    for (int yy = ys; yy < ye; ++yy) {
        float2 a2 = A2[(size_t)yy * 512 + xi];
        float2 b2v = B2[(size_t)yy * 512 + xi];
        rA.x += a2.x;  rA.y += a2.y;
        rB.x += b2v.x; rB.y += b2v.y;
    }

    const int eb = wid * CSTR;
    const int e1 = eb + 2 * lane + 1;

    for (int y = y0; y < y0 + SEG; ++y) {
        int ya = y + RAD;
        if (ya < HH) {
            float2 a2 = A2[(size_t)ya * 512 + xi];
            float2 b2v = B2[(size_t)ya * 512 + xi];
            rA.x += a2.x;  rA.y += a2.y;
            rB.x += b2v.x; rB.y += b2v.y;
        }

        const int buf = y & 1;
        float* E0 = sE[buf][0];
        float* E1 = sE[buf][1];

        float s0 = rA.x + rA.y, s1 = rB.x + rB.y;
        float i0 = s0, i1 = s1;
        WSCAN(i0); WSCAN(i1);
        float x0 = i0 - s0, x1 = i1 - s1;

        if (lane == 0) { E0[eb] = 0.f; E1[eb] = 0.f; }
        E0[e1] = x0 + rA.x; E0[e1 + 1] = i0;
        E1[e1] = x1 + rB.x; E1[e1 + 1] = i1;

        __syncthreads();

        float cnty = (float)(min(y + RAD + 1, HH) - max(y - RAD, 0));
        float2 i2 = I2[(size_t)y * 512 + xi];
        const float* ip = &i2.x;
        float2 ov;
        float* op = &ov.x;
#pragma unroll
        for (int j = 0; j < 2; ++j) {
            float sa = E0[aHi[j]] - E0[aLo[j]] + E0[aT1[j]] + E0[aT2[j]];
            float sb = E1[aHi[j]] - E1[aLo[j]] + E1[aT1[j]] + E1[aT2[j]];
            float inv = 1.0f / (cntx[j] * cnty);
            op[j] = (sa * inv) * ip[j] + (sb * inv);
        }
        O2[(size_t)y * 512 + xi] = ov;

        int yr = y - RAD;
        if (yr >= 0) {
            float2 a2 = A2[(size_t)yr * 512 + xi];
            float2 b2v = B2[(size_t)yr * 512 + xi];
            rA.x -= a2.x;  rA.y -= a2.y;
            rB.x -= b2v.x; rB.y -= b2v.y;
        }
    }
}

extern "C" void kernel_launch(void* const* d_in, const int* in_sizes, int n_in,
                              void* d_out, int out_size) {
    const float* I = (const float*)d_in[0];
    const float* P = (const float*)d_in[1];
    float* out = (float*)d_out;

    dim3 g(HH / SEG, NIMG);
    k_stage1<<<g, NTH>>>(I, P);
    k_stage2<<<g, NTH>>>(I, out);
}

// round 4
// speedup vs baseline: 1.5705x; 1.5705x over previous
#include <cuda_runtime.h>
#include <cuda_bf16.h>

// GuidedFilter (4,3,1024,1024) fp32, R=40, eps=1e-3.
// Two fused kernels. Per output row: vertical running sums in registers (float4,
// 4 cols/thread), horizontal box via warp-local 128-col chunk prefixes
// (window 81 spans <=2 chunks -> 3 LDS/field/pixel). One barrier per row
// (double-buffered prefix arrays).

#define HH   1024
#define WW   1024
#define NIMG 12
#define RAD  40
#define SEG  32
#define NTH  256
#define NW   8                 // warps = chunks of 128 cols
#define CS   136               // padded chunk stride (PID(128)=132)
#define PID(k) ((k) + ((k) >> 5))
#define ESZ  (NW * CS)         // 1088 floats per field per buffer

#define EPS 1e-3f

__device__ float g_a[(size_t)NIMG * HH * WW];
__device__ float g_b[(size_t)NIMG * HH * WW];

#define WSCAN(val)                                                    \
    {                                                                 \
        _Pragma("unroll")                                             \
        for (int o = 1; o < 32; o <<= 1) {                            \
            float _n = __shfl_up_sync(0xffffffffu, (val), o);         \
            if (lane >= o) (val) += _n;                               \
        }                                                             \
    }

// ---------------------------------------------------------------------------
// Stage 1: I,p -> box means of {I,p,Ip,II} -> a,b
// ---------------------------------------------------------------------------
__global__ __launch_bounds__(NTH) void k_stage1(const float* __restrict__ I,
                                                const float* __restrict__ P) {
    __shared__ float sE[2][4][ESZ];

    const int tid  = threadIdx.x;
    const int lane = tid & 31;
    const int w    = tid >> 5;
    const int img  = blockIdx.y;
    const int y0   = blockIdx.x * SEG;
    const size_t b4 = (size_t)img * HH * 256;

    const float4* __restrict__ I4 = (const float4*)I + b4;
    const float4* __restrict__ P4 = (const float4*)P + b4;
    float4* __restrict__ A4 = (float4*)g_a + b4;
    float4* __restrict__ B4 = (float4*)g_b + b4;

    const int c0 = tid * 4;

    // per-column window gather indices
    int aLo[4], aHi[4], aT[4];
    float cntx[4];
#pragma unroll
    for (int j = 0; j < 4; ++j) {
        int c   = c0 + j;
        int lo  = max(c - RAD, 0);
        int hi1 = min(c + RAD, WW - 1);          // inclusive
        int ca  = lo >> 7;
        int cb  = hi1 >> 7;
        aLo[j]  = ca * CS + PID(lo & 127);
        aHi[j]  = cb * CS + PID((hi1 & 127) + 1);
        aT[j]   = ca * CS + ((cb > ca) ? PID(128) : 0);   // P[ca][0] == 0
        cntx[j] = (float)(hi1 + 1 - lo);
    }

    float4 rI = make_float4(0, 0, 0, 0);
    float4 rP = rI, rIp = rI, rII = rI;

    const int ys = max(0, y0 - RAD);
    const int ye = min(HH, y0 + RAD);            // exclusive
#pragma unroll 4
    for (int yy = ys; yy < ye; ++yy) {
        float4 i4 = I4[(size_t)yy * 256 + tid];
        float4 p4 = P4[(size_t)yy * 256 + tid];
        rI.x  += i4.x;        rI.y  += i4.y;        rI.z  += i4.z;        rI.w  += i4.w;
        rP.x  += p4.x;        rP.y  += p4.y;        rP.z  += p4.z;        rP.w  += p4.w;
        rIp.x += i4.x * p4.x; rIp.y += i4.y * p4.y; rIp.z += i4.z * p4.z; rIp.w += i4.w * p4.w;
        rII.x += i4.x * i4.x; rII.y += i4.y * i4.y; rII.z += i4.z * i4.z; rII.w += i4.w * i4.w;
    }

    const int eb = w * CS;
    const int k1 = lane * 4 + 1;
    const int sIdx0 = eb + PID(k1);
    const int sIdx1 = eb + PID(k1 + 1);
    const int sIdx2 = eb + PID(k1 + 2);
    const int sIdx3 = eb + PID(k1 + 3);

    for (int y = y0; y < y0 + SEG; ++y) {
        int ya = y + RAD;
        if (ya < HH) {
            float4 i4 = I4[(size_t)ya * 256 + tid];
            float4 p4 = P4[(size_t)ya * 256 + tid];
            rI.x  += i4.x;        rI.y  += i4.y;        rI.z  += i4.z;        rI.w  += i4.w;
            rP.x  += p4.x;        rP.y  += p4.y;        rP.z  += p4.z;        rP.w  += p4.w;
            rIp.x += i4.x * p4.x; rIp.y += i4.y * p4.y; rIp.z += i4.z * p4.z; rIp.w += i4.w * p4.w;
            rII.x += i4.x * i4.x; rII.y += i4.y * i4.y; rII.z += i4.z * i4.z; rII.w += i4.w * i4.w;
        }

        const int buf = y & 1;
        float* __restrict__ E0 = sE[buf][0];
        float* __restrict__ E1 = sE[buf][1];
        float* __restrict__ E2 = sE[buf][2];
        float* __restrict__ E3 = sE[buf][3];

        // local prefixes over 4 owned cols, per field
        float4 pI, pP, pIp, pII;
        pI.x  = rI.x;  pI.y  = pI.x  + rI.y;  pI.z  = pI.y  + rI.z;  pI.w  = pI.z  + rI.w;
        pP.x  = rP.x;  pP.y  = pP.x  + rP.y;  pP.z  = pP.y  + rP.z;  pP.w  = pP.z  + rP.w;
        pIp.x = rIp.x; pIp.y = pIp.x + rIp.y; pIp.z = pIp.y + rIp.z; pIp.w = pIp.z + rIp.w;
        pII.x = rII.x; pII.y = pII.x + rII.y; pII.z = pII.y + rII.z; pII.w = pII.z + rII.w;

        float s0 = pI.w, s1 = pP.w, s2 = pIp.w, s3 = pII.w;
        float i0 = s0, i1 = s1, i2 = s2, i3 = s3;
        WSCAN(i0); WSCAN(i1); WSCAN(i2); WSCAN(i3);
        float x0 = i0 - s0, x1 = i1 - s1, x2 = i2 - s2, x3 = i3 - s3;

        if (lane == 0) { E0[eb] = 0.f; E1[eb] = 0.f; E2[eb] = 0.f; E3[eb] = 0.f; }
        E0[sIdx0] = x0 + pI.x;  E0[sIdx1] = x0 + pI.y;  E0[sIdx2] = x0 + pI.z;  E0[sIdx3] = x0 + pI.w;
        E1[sIdx0] = x1 + pP.x;  E1[sIdx1] = x1 + pP.y;  E1[sIdx2] = x1 + pP.z;  E1[sIdx3] = x1 + pP.w;
        E2[sIdx0] = x2 + pIp.x; E2[sIdx1] = x2 + pIp.y; E2[sIdx2] = x2 + pIp.z; E2[sIdx3] = x2 + pIp.w;
        E3[sIdx0] = x3 + pII.x; E3[sIdx1] = x3 + pII.y; E3[sIdx2] = x3 + pII.z; E3[sIdx3] = x3 + pII.w;

        __syncthreads();

        float cnty = (float)(min(y + RAD + 1, HH) - max(y - RAD, 0));
        float4 av, bv;
        float* ap = &av.x;
        float* bp = &bv.x;
#pragma unroll
        for (int j = 0; j < 4; ++j) {
            float u0 = E0[aHi[j]] - E0[aLo[j]] + E0[aT[j]];
            float u1 = E1[aHi[j]] - E1[aLo[j]] + E1[aT[j]];
            float u2 = E2[aHi[j]] - E2[aLo[j]] + E2[aT[j]];
            float u3 = E3[aHi[j]] - E3[aLo[j]] + E3[aT[j]];
            float inv = 1.0f / (cntx[j] * cnty);
            float mI  = u0 * inv;
            float mP  = u1 * inv;
            float mIp = u2 * inv;
            float mII = u3 * inv;
            float a = (mIp - mI * mP) / ((mII - mI * mI) + EPS);
            ap[j] = a;
            bp[j] = mP - a * mI;
        }
        A4[(size_t)y * 256 + tid] = av;
        B4[(size_t)y * 256 + tid] = bv;

        int yr = y - RAD;
        if (yr >= 0) {
            float4 i4 = I4[(size_t)yr * 256 + tid];
            float4 p4 = P4[(size_t)yr * 256 + tid];
            rI.x  -= i4.x;        rI.y  -= i4.y;        rI.z  -= i4.z;        rI.w  -= i4.w;
            rP.x  -= p4.x;        rP.y  -= p4.y;        rP.z  -= p4.z;        rP.w  -= p4.w;
            rIp.x -= i4.x * p4.x; rIp.y -= i4.y * p4.y; rIp.z -= i4.z * p4.z; rIp.w -= i4.w * p4.w;
            rII.x -= i4.x * i4.x; rII.y -= i4.y * i4.y; rII.z -= i4.z * i4.z; rII.w -= i4.w * i4.w;
        }
    }
}

// ---------------------------------------------------------------------------
// Stage 2: a,b -> box means -> out = mean_a * I + mean_b
// ---------------------------------------------------------------------------
__global__ __launch_bounds__(NTH) void k_stage2(const float* __restrict__ I,
                                                float* __restrict__ out) {
    __shared__ float sE[2][2][ESZ];

    const int tid  = threadIdx.x;
    const int lane = tid & 31;
    const int w    = tid >> 5;
    const int img  = blockIdx.y;
    const int y0   = blockIdx.x * SEG;
    const size_t b4 = (size_t)img * HH * 256;

    const float4* __restrict__ A4 = (const float4*)g_a + b4;
    const float4* __restrict__ B4 = (const float4*)g_b + b4;
    const float4* __restrict__ I4 = (const float4*)I + b4;
    float4* __restrict__ O4 = (float4*)out + b4;

    const int c0 = tid * 4;

    int aLo[4], aHi[4], aT[4];
    float cntx[4];
#pragma unroll
    for (int j = 0; j < 4; ++j) {
        int c   = c0 + j;
        int lo  = max(c - RAD, 0);
        int hi1 = min(c + RAD, WW - 1);
        int ca  = lo >> 7;
        int cb  = hi1 >> 7;
        aLo[j]  = ca * CS + PID(lo & 127);
        aHi[j]  = cb * CS + PID((hi1 & 127) + 1);
        aT[j]   = ca * CS + ((cb > ca) ? PID(128) : 0);
        cntx[j] = (float)(hi1 + 1 - lo);
    }

    float4 rA = make_float4(0, 0, 0, 0);
    float4 rB = rA;

    const int ys = max(0, y0 - RAD);
    const int ye = min(HH, y0 + RAD);
#pragma unroll 4
    for (int yy = ys; yy < ye; ++yy) {
        float4 a4 = A4[(size_t)yy * 256 + tid];
        float4 b4v = B4[(size_t)yy * 256 + tid];
        rA.x += a4.x;  rA.y += a4.y;  rA.z += a4.z;  rA.w += a4.w;
        rB.x += b4v.x; rB.y += b4v.y; rB.z += b4v.z; rB.w += b4v.w;
    }

    const int eb = w * CS;
    const int k1 = lane * 4 + 1;
    const int sIdx0 = eb + PID(k1);
    const int sIdx1 = eb + PID(k1 + 1);
    const int sIdx2 = eb + PID(k1 + 2);
    const int sIdx3 = eb + PID(k1 + 3);

    for (int y = y0; y < y0 + SEG; ++y) {
        int ya = y + RAD;
        if (ya < HH) {
            float4 a4 = A4[(size_t)ya * 256 + tid];
            float4 b4v = B4[(size_t)ya * 256 + tid];
            rA.x += a4.x;  rA.y += a4.y;  rA.z += a4.z;  rA.w += a4.w;
            rB.x += b4v.x; rB.y += b4v.y; rB.z += b4v.z; rB.w += b4v.w;
        }

        const int buf = y & 1;
        float* __restrict__ E0 = sE[buf][0];
        float* __restrict__ E1 = sE[buf][1];

        float4 pA, pB;
        pA.x = rA.x; pA.y = pA.x + rA.y; pA.z = pA.y + rA.z; pA.w = pA.z + rA.w;
        pB.x = rB.x; pB.y = pB.x + rB.y; pB.z = pB.y + rB.z; pB.w = pB.z + rB.w;

        float s0 = pA.w, s1 = pB.w;
        float i0 = s0, i1 = s1;
        WSCAN(i0); WSCAN(i1);
        float x0 = i0 - s0, x1 = i1 - s1;

        if (lane == 0) { E0[eb] = 0.f; E1[eb] = 0.f; }
        E0[sIdx0] = x0 + pA.x; E0[sIdx1] = x0 + pA.y; E0[sIdx2] = x0 + pA.z; E0[sIdx3] = x0 + pA.w;
        E1[sIdx0] = x1 + pB.x; E1[sIdx1] = x1 + pB.y; E1[sIdx2] = x1 + pB.z; E1[sIdx3] = x1 + pB.w;

        __syncthreads();

        float cnty = (float)(min(y + RAD + 1, HH) - max(y - RAD, 0));
        float4 i4 = I4[(size_t)y * 256 + tid];
        const float* ip = &i4.x;
        float4 ov;
        float* op = &ov.x;
#pragma unroll
        for (int j = 0; j < 4; ++j) {
            float sa = E0[aHi[j]] - E0[aLo[j]] + E0[aT[j]];
            float sb = E1[aHi[j]] - E1[aLo[j]] + E1[aT[j]];
            float inv = 1.0f / (cntx[j] * cnty);
            op[j] = (sa * inv) * ip[j] + (sb * inv);
        }
        O4[(size_t)y * 256 + tid] = ov;

        int yr = y - RAD;
        if (yr >= 0) {
            float4 a4 = A4[(size_t)yr * 256 + tid];
            float4 b4v = B4[(size_t)yr * 256 + tid];
            rA.x -= a4.x;  rA.y -= a4.y;  rA.z -= a4.z;  rA.w -= a4.w;
            rB.x -= b4v.x; rB.y -= b4v.y; rB.z -= b4v.z; rB.w -= b4v.w;
        }
    }
}

extern "C" void kernel_launch(void* const* d_in, const int* in_sizes, int n_in,
                              void* d_out, int out_size) {
    const float* I = (const float*)d_in[0];
    const float* P = (const float*)d_in[1];
    float* out = (float*)d_out;

    dim3 g(HH / SEG, NIMG);
    k_stage1<<<g, NTH>>>(I, P);
    k_stage2<<<g, NTH>>>(I, out);
}